// round 3
// baseline (speedup 1.0000x reference)
#include <cuda_runtime.h>
#include <math.h>
#include <float.h>
#include <limits.h>

#define NB   32
#define NM   10000
#define ND   512
#define KTOP 5
#define RV   32768            // 32*32*32 voxels per memory slot

#define BN   64               // m-tile per block (== blockDim.x)
#define KC   64               // k-chunk
#define KP   68               // row pad: stride 272B == 16 mod 128 -> phase-conflict-free

// ---- device scratch ----
__device__ float g_sim[NB * NM];
__device__ int   g_topidx[NB * KTOP];
__device__ float g_topval[NB * KTOP];

// ---------------- kernel 1: sim (x-norms fused) ----------------
// Block: 64 threads. Thread tid owns m-column m0+tid and all 8 b-rows.
// ka: LDS.128 per 4-k (conflict-free via KP=68); xa: broadcast LDS.128 (free).
__global__ __launch_bounds__(64) void sim_kernel(const float* __restrict__ x,
                                                 const float* __restrict__ keys) {
    __shared__ float xs[8 * KP];      // x chunk   [8][KP]
    __shared__ float ks[BN * KP];     // key chunk [64][KP]
    __shared__ float xsq[8];          // per-b ||x||^2

    const int tid = threadIdx.x;
    const int m0  = blockIdx.x * BN;
    const int b0  = blockIdx.y * 8;
    const int gm  = m0 + tid;

    float acc[8] = {};
    float kq = 0.f, xq = 0.f;

    for (int c = 0; c < ND / KC; ++c) {
        const int k0_4 = c * (KC / 4);
        // x chunk: 8 rows x 16 float4 = 128 loads, 2 per thread (coalesced)
        {
            const float4* xg = reinterpret_cast<const float4*>(x);
#pragma unroll
            for (int t = 0; t < 2; ++t) {
                int idx = tid + t * 64;
                int row = idx >> 4, c4 = idx & 15;
                float4 v = xg[(b0 + row) * (ND / 4) + k0_4 + c4];
                *reinterpret_cast<float4*>(xs + row * KP + c4 * 4) = v;
            }
        }
        // key chunk: 64 rows x 16 float4 = 1024 loads, 16 per thread (coalesced)
        {
            const float4* kg = reinterpret_cast<const float4*>(keys);
#pragma unroll
            for (int t = 0; t < 16; ++t) {
                int idx = tid + t * 64;
                int row = idx >> 4, c4 = idx & 15;
                int gr  = m0 + row;
                float4 v = make_float4(0.f, 0.f, 0.f, 0.f);
                if (gr < NM) v = kg[gr * (ND / 4) + k0_4 + c4];
                *reinterpret_cast<float4*>(ks + row * KP + c4 * 4) = v;
            }
        }
        __syncthreads();

        // key-norm partial: thread scans its OWN row (float4, phase-conflict-free)
        {
            const float* kr = ks + tid * KP;
#pragma unroll
            for (int c4 = 0; c4 < 16; ++c4) {
                float4 v = *reinterpret_cast<const float4*>(kr + c4 * 4);
                kq += v.x * v.x + v.y * v.y + v.z * v.z + v.w * v.w;
            }
        }
        // x-norm partial: threads 0..7 scan xs rows
        if (tid < 8) {
            const float* xr = xs + tid * KP;
#pragma unroll
            for (int c4 = 0; c4 < 16; ++c4) {
                float4 v = *reinterpret_cast<const float4*>(xr + c4 * 4);
                xq += v.x * v.x + v.y * v.y + v.z * v.z + v.w * v.w;
            }
        }

        // main FMA loop: per kk = 1 LDS.128 (ka) + 8 broadcast LDS.128 (xa) + 32 FFMA
        const float* kr = ks + tid * KP;
#pragma unroll 4
        for (int kk = 0; kk < KC / 4; ++kk) {
            float4 ka = *reinterpret_cast<const float4*>(kr + kk * 4);
#pragma unroll
            for (int b = 0; b < 8; ++b) {
                float4 xa = *reinterpret_cast<const float4*>(xs + b * KP + kk * 4);
                acc[b] += xa.x * ka.x + xa.y * ka.y + xa.z * ka.z + xa.w * ka.w;
            }
        }
        __syncthreads();
    }

    if (tid < 8) xsq[tid] = xq;
    __syncthreads();

    if (gm < NM) {
        float invk = 1.f / fmaxf(sqrtf(kq), 1e-12f);
#pragma unroll
        for (int b = 0; b < 8; ++b) {
            float invx = 1.f / fmaxf(sqrtf(xsq[b]), 1e-12f);
            g_sim[(b0 + b) * NM + gm] = acc[b] * invx * invk;
        }
    }
}

// ---------------- kernel 2: top-5 per batch row ----------------
// Per-thread register top-5, then 5 argmax rounds over the 1280-candidate pool.
// Tie-break matches jax.lax.top_k (equal value -> lower index first).
__global__ __launch_bounds__(256) void topk_kernel(float* __restrict__ out,
                                                   long long out_size) {
    __shared__ float sv[256 * KTOP];
    __shared__ int   si[256 * KTOP];
    __shared__ float wv[8];
    __shared__ int   wi[8];
    __shared__ int   wp[8];

    const int b = blockIdx.x, tid = threadIdx.x;
    const int lane = tid & 31, warp = tid >> 5;

    float v[KTOP]; int ix[KTOP];
#pragma unroll
    for (int p = 0; p < KTOP; ++p) { v[p] = -FLT_MAX; ix[p] = INT_MAX; }

    const float* row = g_sim + b * NM;
    for (int i = tid; i < NM; i += 256) {
        float val = row[i];
        if (val > v[KTOP - 1]) {                 // ascending i -> ties keep lower idx
            v[KTOP - 1] = val; ix[KTOP - 1] = i;
#pragma unroll
            for (int q = KTOP - 1; q > 0; --q) {
                if (v[q] > v[q - 1]) {
                    float tv = v[q]; v[q] = v[q - 1]; v[q - 1] = tv;
                    int   ti = ix[q]; ix[q] = ix[q - 1]; ix[q - 1] = ti;
                }
            }
        }
    }
#pragma unroll
    for (int p = 0; p < KTOP; ++p) { sv[p * 256 + tid] = v[p]; si[p * 256 + tid] = ix[p]; }
    __syncthreads();

    for (int k = 0; k < KTOP; ++k) {
        float bv = -FLT_MAX; int bi = INT_MAX; int bp = -1;
#pragma unroll
        for (int t = 0; t < KTOP; ++t) {
            int j = t * 256 + tid;
            float vv = sv[j]; int ii = si[j];
            if (vv > bv || (vv == bv && ii < bi)) { bv = vv; bi = ii; bp = j; }
        }
#pragma unroll
        for (int o = 16; o > 0; o >>= 1) {
            float ov = __shfl_down_sync(0xffffffffu, bv, o);
            int   oi = __shfl_down_sync(0xffffffffu, bi, o);
            int   op = __shfl_down_sync(0xffffffffu, bp, o);
            if (ov > bv || (ov == bv && oi < bi)) { bv = ov; bi = oi; bp = op; }
        }
        if (lane == 0) { wv[warp] = bv; wi[warp] = bi; wp[warp] = bp; }
        __syncthreads();
        if (tid == 0) {
            float fv = wv[0]; int fi = wi[0]; int fp = wp[0];
#pragma unroll
            for (int w = 1; w < 8; ++w) {
                if (wv[w] > fv || (wv[w] == fv && wi[w] < fi)) {
                    fv = wv[w]; fi = wi[w]; fp = wp[w];
                }
            }
            g_topidx[b * KTOP + k] = fi;
            g_topval[b * KTOP + k] = fv;
            sv[fp] = -FLT_MAX;                   // mask winner
            const long long base = (long long)NB * KTOP * RV;
            if (out_size >= base + 2LL * NB * KTOP) {
                out[base + b * KTOP + k]             = (float)fi;
                out[base + NB * KTOP + b * KTOP + k] = fv;
            }
        }
        __syncthreads();
    }
}

// ---------------- kernel 3: gather (4 blocks/slot, 8 float4/thread) ----------------
__global__ __launch_bounds__(256) void gather_kernel(const float* __restrict__ mv,
                                                     float* __restrict__ out) {
    const int p    = blockIdx.x >> 2;           // slot pair (b*KTOP+k)
    const int part = blockIdx.x & 3;            // 1/4 of the voxel grid (32 KB)
    const int idx  = g_topidx[p];
    const float4* src = reinterpret_cast<const float4*>(mv + (long long)idx * RV) + part * 2048;
    float4*       dst = reinterpret_cast<float4*>(out + (long long)p * RV) + part * 2048;

    float4 r[8];
#pragma unroll
    for (int j = 0; j < 8; ++j) r[j] = src[threadIdx.x + j * 256];   // 8 loads in flight
#pragma unroll
    for (int j = 0; j < 8; ++j) dst[threadIdx.x + j * 256] = r[j];
}

extern "C" void kernel_launch(void* const* d_in, const int* in_sizes, int n_in,
                              void* d_out, int out_size) {
    const float* x    = (const float*)d_in[0];
    const float* keys = (const float*)d_in[1];
    const float* mv   = (const float*)d_in[2];
    float* out = (float*)d_out;

    dim3 simgrid((NM + BN - 1) / BN, 4);
    sim_kernel<<<simgrid, BN>>>(x, keys);
    topk_kernel<<<NB, 256>>>(out, (long long)out_size);
    gather_kernel<<<NB * KTOP * 4, 256>>>(mv, out);
}

// round 4
// speedup vs baseline: 1.1485x; 1.1485x over previous
#include <cuda_runtime.h>
#include <math.h>
#include <float.h>
#include <limits.h>

#define NB     32
#define NM     10000
#define ND     512
#define KTOP   5
#define RV     32768          // 32*32*32 voxels per slot
#define RV4    8192           // in float4
#define BN     64             // m-tile per block (== blockDim.x)
#define KC     64             // k-chunk
#define KP     68             // smem row pad: 272B stride -> phase-conflict-free LDS.128
#define KSPLIT 2
#define KHALF  (ND / KSPLIT)  // 256

typedef unsigned long long ull;

// packed fp32x2 FMA (sm_10x FFMA2) — full fp32 precision per lane
#define FMA_F32X2(d, a, b, c) \
    asm("fma.rn.f32x2 %0, %1, %2, %3;" : "=l"(d) : "l"(a), "l"(b), "l"(c))

__device__ __forceinline__ float ull_sum2(ull v) {
    return __uint_as_float((unsigned)v) + __uint_as_float((unsigned)(v >> 32));
}

// ---- device scratch ----
__device__ float g_part[KSPLIT * NB * NM];   // partial dot [z][b][m]
__device__ float g_kq[KSPLIT * NM];          // partial ||k||^2 [z][m]
__device__ float g_invx[NB];
__device__ int   g_topidx[NB * KTOP];

// ---------------- kernel 0: 1/||x_b|| ----------------
__global__ void xnorm_kernel(const float* __restrict__ x) {
    int b    = threadIdx.x >> 5;
    int lane = threadIdx.x & 31;
    const float4* x4 = reinterpret_cast<const float4*>(x) + b * (ND / 4);
    float s = 0.f;
#pragma unroll
    for (int j = 0; j < 4; ++j) {
        float4 v = x4[j * 32 + lane];
        s += v.x * v.x + v.y * v.y + v.z * v.z + v.w * v.w;
    }
#pragma unroll
    for (int o = 16; o > 0; o >>= 1) s += __shfl_xor_sync(0xffffffffu, s, o);
    if (lane == 0) g_invx[b] = 1.f / fmaxf(sqrtf(s), 1e-12f);
}

// ---------------- kernel 1: sim partials (K-split x2, FFMA2) ----------------
// Grid (157, 4, 2), 64 threads. Thread owns m-col m0+tid, 8 b-rows, 256 k.
__global__ __launch_bounds__(64) void sim_stage(const float* __restrict__ x,
                                                const float* __restrict__ keys) {
    __shared__ float xs[8 * KP];
    __shared__ float ks[BN * KP];

    const int tid = threadIdx.x;
    const int m0  = blockIdx.x * BN;
    const int b0  = blockIdx.y * 8;
    const int kz  = blockIdx.z * KHALF;
    const int gm  = m0 + tid;

    ull acc2[8] = {};
    ull kq2 = 0;

    for (int c = 0; c < KHALF / KC; ++c) {
        const int k0_4 = (kz + c * KC) >> 2;
        // x chunk: 8 rows x 16 float4, 2 per thread (coalesced)
        {
            const float4* xg = reinterpret_cast<const float4*>(x);
#pragma unroll
            for (int t = 0; t < 2; ++t) {
                int idx = tid + t * 64;
                int row = idx >> 4, c4 = idx & 15;
                *reinterpret_cast<float4*>(xs + row * KP + c4 * 4) =
                    xg[(b0 + row) * (ND / 4) + k0_4 + c4];
            }
        }
        // key chunk: 64 rows x 16 float4, 16 per thread (coalesced, zero-pad)
        {
            const float4* kg = reinterpret_cast<const float4*>(keys);
#pragma unroll
            for (int t = 0; t < 16; ++t) {
                int idx = tid + t * 64;
                int row = idx >> 4, c4 = idx & 15;
                int gr  = m0 + row;
                float4 v = make_float4(0.f, 0.f, 0.f, 0.f);
                if (gr < NM) v = kg[gr * (ND / 4) + k0_4 + c4];
                *reinterpret_cast<float4*>(ks + row * KP + c4 * 4) = v;
            }
        }
        __syncthreads();

        // per kk: 1 LDS.128 ka + 8 broadcast LDS.128 xa + 18 FFMA2
        const ulonglong2* kr2 = reinterpret_cast<const ulonglong2*>(ks + tid * KP);
#pragma unroll 4
        for (int kk = 0; kk < KC / 4; ++kk) {
            ulonglong2 ka = kr2[kk];
            FMA_F32X2(kq2, ka.x, ka.x, kq2);     // ||k||^2 from registers
            FMA_F32X2(kq2, ka.y, ka.y, kq2);
#pragma unroll
            for (int b = 0; b < 8; ++b) {
                ulonglong2 xa = *reinterpret_cast<const ulonglong2*>(xs + b * KP + kk * 4);
                FMA_F32X2(acc2[b], xa.x, ka.x, acc2[b]);
                FMA_F32X2(acc2[b], xa.y, ka.y, acc2[b]);
            }
        }
        __syncthreads();
    }

    if (gm < NM) {
#pragma unroll
        for (int b = 0; b < 8; ++b)
            g_part[(blockIdx.z * NB + b0 + b) * NM + gm] = ull_sum2(acc2[b]);
        if (blockIdx.y == 0)
            g_kq[blockIdx.z * NM + gm] = ull_sum2(kq2);
    }
}

// ---------------- kernel 2: fused normalize + top-5 ----------------
// One 1024-thread block per b. sim computed on the fly from partials.
// Tie-break matches jax.lax.top_k (equal value -> lower index first).
__global__ __launch_bounds__(1024) void topk_fused(float* __restrict__ out,
                                                   long long out_size) {
    __shared__ float sv[1024 * KTOP];
    __shared__ int   si[1024 * KTOP];
    __shared__ float wv[32];
    __shared__ int   wi[32];
    __shared__ int   wp[32];

    const int b = blockIdx.x, tid = threadIdx.x;
    const int lane = tid & 31, warp = tid >> 5;
    const float invx = g_invx[b];

    float v[KTOP]; int ix[KTOP];
#pragma unroll
    for (int p = 0; p < KTOP; ++p) { v[p] = -FLT_MAX; ix[p] = INT_MAX; }

    const float* p0 = g_part + b * NM;
    const float* p1 = g_part + (NB + b) * NM;
    for (int i = tid; i < NM; i += 1024) {
        float dot = p0[i] + p1[i];
        float kq  = g_kq[i] + g_kq[NM + i];
        float val = dot * invx * (1.f / fmaxf(sqrtf(kq), 1e-12f));
        if (val > v[KTOP - 1]) {                 // ascending i -> ties keep lower idx
            v[KTOP - 1] = val; ix[KTOP - 1] = i;
#pragma unroll
            for (int q = KTOP - 1; q > 0; --q) {
                if (v[q] > v[q - 1]) {
                    float tv = v[q]; v[q] = v[q - 1]; v[q - 1] = tv;
                    int   ti = ix[q]; ix[q] = ix[q - 1]; ix[q - 1] = ti;
                }
            }
        }
    }
#pragma unroll
    for (int p = 0; p < KTOP; ++p) { sv[p * 1024 + tid] = v[p]; si[p * 1024 + tid] = ix[p]; }
    __syncthreads();

    for (int k = 0; k < KTOP; ++k) {
        float bv = -FLT_MAX; int bi = INT_MAX; int bp = -1;
#pragma unroll
        for (int t = 0; t < KTOP; ++t) {
            int j = t * 1024 + tid;
            float vv = sv[j]; int ii = si[j];
            if (vv > bv || (vv == bv && ii < bi)) { bv = vv; bi = ii; bp = j; }
        }
#pragma unroll
        for (int o = 16; o > 0; o >>= 1) {
            float ov = __shfl_down_sync(0xffffffffu, bv, o);
            int   oi = __shfl_down_sync(0xffffffffu, bi, o);
            int   op = __shfl_down_sync(0xffffffffu, bp, o);
            if (ov > bv || (ov == bv && oi < bi)) { bv = ov; bi = oi; bp = op; }
        }
        if (lane == 0) { wv[warp] = bv; wi[warp] = bi; wp[warp] = bp; }
        __syncthreads();
        if (tid == 0) {
            float fv = wv[0]; int fi = wi[0]; int fp = wp[0];
#pragma unroll
            for (int w = 1; w < 32; ++w) {
                if (wv[w] > fv || (wv[w] == fv && wi[w] < fi)) {
                    fv = wv[w]; fi = wi[w]; fp = wp[w];
                }
            }
            g_topidx[b * KTOP + k] = fi;
            sv[fp] = -FLT_MAX;                   // mask winner
            const long long base = (long long)NB * KTOP * RV;
            if (out_size >= base + 2LL * NB * KTOP) {
                out[base + b * KTOP + k]             = (float)fi;
                out[base + NB * KTOP + b * KTOP + k] = fv;
            }
        }
        __syncthreads();
    }
}

// ---------------- kernel 3: gather (exact-fit grid-stride, 4 f4/thread) ----------------
// 1280 blocks x 256 thr x 4 float4 == 160 slots * 8192 float4 exactly.
// stride = 40 slots -> per-thread slot = slot0 + 40j, constant offset.
__global__ __launch_bounds__(256) void gather_kernel(const float* __restrict__ mv,
                                                     float* __restrict__ out) {
    const int i0    = blockIdx.x * 256 + threadIdx.x;   // float4 index
    const int slot0 = i0 >> 13;                          // /8192
    const int off   = i0 & 8191;

    int idx[4];
#pragma unroll
    for (int j = 0; j < 4; ++j) idx[j] = g_topidx[slot0 + j * 40];

    const float4* src = reinterpret_cast<const float4*>(mv);
    float4*       dst = reinterpret_cast<float4*>(out);
    float4 r[4];
#pragma unroll
    for (int j = 0; j < 4; ++j) r[j] = src[(long long)idx[j] * RV4 + off];
#pragma unroll
    for (int j = 0; j < 4; ++j) dst[(long long)(slot0 + j * 40) * RV4 + off] = r[j];
}

extern "C" void kernel_launch(void* const* d_in, const int* in_sizes, int n_in,
                              void* d_out, int out_size) {
    const float* x    = (const float*)d_in[0];
    const float* keys = (const float*)d_in[1];
    const float* mv   = (const float*)d_in[2];
    float* out = (float*)d_out;

    xnorm_kernel<<<1, 1024>>>(x);
    dim3 simgrid((NM + BN - 1) / BN, NB / 8, KSPLIT);
    sim_stage<<<simgrid, BN>>>(x, keys);
    topk_fused<<<NB, 1024>>>(out, (long long)out_size);
    gather_kernel<<<1280, 256>>>(mv, out);
}